// round 16
// baseline (speedup 1.0000x reference)
#include <cuda_runtime.h>
#include <cuda_fp16.h>
#include <cstdint>

#define D 128
#define MAXN 100000
#define MAXE 600000
#define SCAN_NB ((MAXN + 255) / 256)   // 391

// Scratch (device globals; no allocs allowed)
__device__ __half g_srcH[(size_t)MAXN * D];  // 25.6 MB fp16 src cache
__device__ __half g_U[(size_t)MAXN * D];     // 25.6 MB: fp16(dst + A)
__device__ __half g_V[(size_t)MAXN * D];     // 25.6 MB: fp16(dst * A)
__device__ __half g_WiH[D * D];              // fp16 W_intra
__device__ __half g_WnH[D * D];              // fp16 W_inter
__device__ int    g_count[MAXN];             // zeroed by scan each run
__device__ int    g_offs[MAXN];
__device__ int    g_state[SCAN_NB];          // lookback state; re-armed by permute
__device__ float2 g_meta[MAXE];              // (.x = src id bits, .y = w)

// ---------------------------------------------------------------------------
// Kernel 0: histogram of dst + W -> fp16 (small, ~4us)
// ---------------------------------------------------------------------------
__global__ void hist_w_kernel(const float* __restrict__ Wi,
                              const float* __restrict__ Wn,
                              const int* __restrict__ ei, int E) {
    int i = blockIdx.x * blockDim.x + threadIdx.x;
    if (i < 2 * (D * D / 8)) {                 // 4096 threads: W conversion
        bool second = i >= (D * D / 8);
        int j = second ? i - D * D / 8 : i;
        const float* W = second ? Wn : Wi;
        __half* WH = second ? g_WnH : g_WiH;
        float4 a = __ldg((const float4*)W + 2 * j);
        float4 b = __ldg((const float4*)W + 2 * j + 1);
        __half2 h0 = __floats2half2_rn(a.x, a.y);
        __half2 h1 = __floats2half2_rn(a.z, a.w);
        __half2 h2 = __floats2half2_rn(b.x, b.y);
        __half2 h3 = __floats2half2_rn(b.z, b.w);
        uint4 o;
        o.x = *(uint32_t*)&h0;
        o.y = *(uint32_t*)&h1;
        o.z = *(uint32_t*)&h2;
        o.w = *(uint32_t*)&h3;
        ((uint4*)WH)[j] = o;
    }
    if (i < E) atomicAdd(&g_count[__ldg(&ei[E + i])], 1);
}

// ---------------------------------------------------------------------------
// Kernel 1: single-pass exclusive scan (decoupled lookback) — R9 verbatim
// ---------------------------------------------------------------------------
__global__ __launch_bounds__(256) void scan_kernel(int N) {
    __shared__ int ws[8];
    __shared__ int s_prefix;
    int tid = threadIdx.x, lane = tid & 31, wrp = tid >> 5;
    int b = blockIdx.x;
    int i = b * 256 + tid;
    int c = (i < N) ? g_count[i] : 0;
    if (i < N) g_count[i] = 0;

    int v = c;
#pragma unroll
    for (int o = 1; o < 32; o <<= 1) {
        int t = __shfl_up_sync(0xffffffffu, v, o);
        if (lane >= o) v += t;
    }
    if (lane == 31) ws[wrp] = v;
    __syncthreads();
    if (wrp == 0) {
        int s = (lane < 8) ? ws[lane] : 0;
#pragma unroll
        for (int o = 1; o < 8; o <<= 1) {
            int t = __shfl_up_sync(0xffffffffu, s, o);
            if (lane >= o) s += t;
        }
        if (lane < 8) ws[lane] = s;
    }
    __syncthreads();
    int incl = v + ((wrp > 0) ? ws[wrp - 1] : 0);
    int total = ws[7];

    if (tid == 0) {
        __threadfence();
        if (b == 0) {
            atomicExch(&g_state[0], (2 << 24) | total);
            s_prefix = 0;
        } else {
            atomicExch(&g_state[b], (1 << 24) | total);
        }
    }

    if (b > 0 && wrp == 0) {
        int agg = 0;
        int p_hi = b - 1;
        while (true) {
            int p = p_hi - lane;
            int st = (p >= 0) ? atomicAdd(&g_state[p], 0) : (2 << 24);
            int flag = st >> 24;
            int val = st & 0xFFFFFF;
            unsigned m2 = __ballot_sync(0xffffffffu, flag == 2);
            unsigned m0 = __ballot_sync(0xffffffffu, flag == 0);
            if (m2) {
                int k = __ffs(m2) - 1;
                if (m0 & ((1u << k) - 1)) continue;
                int vv = (lane <= k) ? val : 0;
#pragma unroll
                for (int o = 16; o; o >>= 1) vv += __shfl_down_sync(0xffffffffu, vv, o);
                vv = __shfl_sync(0xffffffffu, vv, 0);
                agg += vv;
                break;
            } else {
                if (m0) continue;
                int vv = val;
#pragma unroll
                for (int o = 16; o; o >>= 1) vv += __shfl_down_sync(0xffffffffu, vv, o);
                vv = __shfl_sync(0xffffffffu, vv, 0);
                agg += vv;
                p_hi -= 32;
            }
        }
        if (lane == 0) {
            s_prefix = agg;
            __threadfence();
            atomicExch(&g_state[b], (2 << 24) | (agg + total));
        }
    }
    __syncthreads();
    if (i < N) g_offs[i] = s_prefix + incl - c;
}

// ---------------------------------------------------------------------------
// Kernel 2: permute + src->fp16 convert co-scheduled — R15 verbatim
// ---------------------------------------------------------------------------
__global__ void permute_convert_kernel(const float* __restrict__ src,
                                       const int* __restrict__ ei,
                                       const float* __restrict__ ew,
                                       int E, int n8, int nb) {
    int i = blockIdx.x * blockDim.x + threadIdx.x;
    if (i < nb) g_state[i] = 0;
    if (i < n8) {
        float4 a = __ldg((const float4*)src + 2 * i);
        float4 b = __ldg((const float4*)src + 2 * i + 1);
        __half2 h0 = __floats2half2_rn(a.x, a.y);
        __half2 h1 = __floats2half2_rn(a.z, a.w);
        __half2 h2 = __floats2half2_rn(b.x, b.y);
        __half2 h3 = __floats2half2_rn(b.z, b.w);
        uint4 o;
        o.x = *(uint32_t*)&h0;
        o.y = *(uint32_t*)&h1;
        o.z = *(uint32_t*)&h2;
        o.w = *(uint32_t*)&h3;
        ((uint4*)g_srcH)[i] = o;
    }
    if (i < E) {
        int dst = __ldg(&ei[E + i]);
        int srcid = __ldg(&ei[i]);
        float w = __ldg(&ew[i]);
        int pos = atomicAdd(&g_offs[dst], 1);
        g_meta[pos] = make_float2(__int_as_float(srcid), w);
    }
}

// ---------------------------------------------------------------------------
// Kernel 3: gather — 8-deep row-load batches (uint2 fp16 rows), so a typical
// degree-6 node's whole segment is ONE batch of concurrent L2 loads.
// ---------------------------------------------------------------------------
__global__ __launch_bounds__(256) void gather_kernel(
    const float* __restrict__ dstx, int N) {
    int w = (blockIdx.x * 256 + threadIdx.x) >> 5;
    int lane = threadIdx.x & 31;
    if (w >= N) return;
    int end = __ldg(&g_offs[w]);
    int base = (w > 0) ? __ldg(&g_offs[w - 1]) : 0;
    int deg = end - base;
    float4 dv = __ldg((const float4*)(dstx + (size_t)w * D) + lane);
    float4 acc = make_float4(0.f, 0.f, 0.f, 0.f);

    for (int c0 = 0; c0 < deg; c0 += 32) {
        int cn = min(deg - c0, 32);
        float2 mv = make_float2(0.f, 0.f);
        if (lane < cn) mv = __ldg(&g_meta[base + c0 + lane]);
        for (int j = 0; j < cn; j += 8) {
            uint2 h[8];
            float wv[8];
#pragma unroll
            for (int u = 0; u < 8; ++u) {
                int idx = j + u;
                int su = __shfl_sync(0xffffffffu, __float_as_int(mv.x), idx & 31);
                float wu = __shfl_sync(0xffffffffu, mv.y, idx & 31);
                bool valid = idx < cn;
                wv[u] = valid ? wu : 0.f;
                if (valid)
                    h[u] = __ldg((const uint2*)(g_srcH + (size_t)su * D) + lane);
                else
                    h[u] = make_uint2(0u, 0u);
            }
#pragma unroll
            for (int u = 0; u < 8; ++u) {
                float2 f01 = __half22float2(*(__half2*)&h[u].x);
                float2 f23 = __half22float2(*(__half2*)&h[u].y);
                acc.x += wv[u] * f01.x;
                acc.y += wv[u] * f01.y;
                acc.z += wv[u] * f23.x;
                acc.w += wv[u] * f23.y;
            }
        }
    }
    __half2 u0 = __floats2half2_rn(dv.x + acc.x, dv.y + acc.y);
    __half2 u1 = __floats2half2_rn(dv.z + acc.z, dv.w + acc.w);
    __half2 v0 = __floats2half2_rn(dv.x * acc.x, dv.y * acc.y);
    __half2 v1 = __floats2half2_rn(dv.z * acc.z, dv.w * acc.w);
    ((uint2*)(g_U + (size_t)w * D))[lane] = make_uint2(*(uint32_t*)&u0, *(uint32_t*)&u1);
    ((uint2*)(g_V + (size_t)w * D))[lane] = make_uint2(*(uint32_t*)&v0, *(uint32_t*)&v1);
}

// ---------------------------------------------------------------------------
// Kernel 4: dual GEMM + leaky_relu, fp16 mma.m16n8k16 — R14 verbatim
// ---------------------------------------------------------------------------
#define SSTR 136

__device__ __forceinline__ void mma_f16(float c[4], const uint32_t a[4],
                                        const uint32_t b[2]) {
    asm volatile(
        "mma.sync.aligned.m16n8k16.row.col.f32.f16.f16.f32 "
        "{%0,%1,%2,%3},{%4,%5,%6,%7},{%8,%9},{%0,%1,%2,%3};"
        : "+f"(c[0]), "+f"(c[1]), "+f"(c[2]), "+f"(c[3])
        : "r"(a[0]), "r"(a[1]), "r"(a[2]), "r"(a[3]), "r"(b[0]), "r"(b[1]));
}

__global__ __launch_bounds__(256) void fused_gemm_tc_kernel(
    float* __restrict__ out, int N) {

    __shared__ uint32_t u_s[16][SSTR];
    __shared__ uint32_t v_s[16][SSTR];
    __shared__ uint32_t wi_s[16][SSTR];
    __shared__ uint32_t wn_s[16][SSTR];

    const int tid = threadIdx.x;
    const int lane = tid & 31;
    const int wid = tid >> 5;
    const int wm = wid >> 2;     // 0..1
    const int wn = wid & 3;      // 0..3
    const int grp = lane >> 2;   // 0..7
    const int qid = lane & 3;    // 0..3
    const int row0 = blockIdx.x * 128;

    const int fm = tid >> 1;          // 0..127
    const int fkq = (tid & 1) * 8;    // kp word offset: 0 or 8
    const int frow = row0 + fm;
    const bool frow_ok = frow < N;

    float acc[4][4][4];
#pragma unroll
    for (int mt = 0; mt < 4; ++mt)
#pragma unroll
        for (int nt = 0; nt < 4; ++nt)
#pragma unroll
            for (int c = 0; c < 4; ++c) acc[mt][nt][c] = 0.f;

    for (int kt = 0; kt < 4; ++kt) {
        const int k0 = kt * 32 + fkq * 2;
        {
            uint4 ua = make_uint4(0, 0, 0, 0), ub = ua;
            if (frow_ok) {
                const uint4* up = (const uint4*)(g_U + (size_t)frow * D + k0);
                ua = __ldg(up); ub = __ldg(up + 1);
            }
            u_s[fkq + 0][fm] = ua.x; u_s[fkq + 1][fm] = ua.y;
            u_s[fkq + 2][fm] = ua.z; u_s[fkq + 3][fm] = ua.w;
            u_s[fkq + 4][fm] = ub.x; u_s[fkq + 5][fm] = ub.y;
            u_s[fkq + 6][fm] = ub.z; u_s[fkq + 7][fm] = ub.w;
            uint4 va = make_uint4(0, 0, 0, 0), vb = va;
            if (frow_ok) {
                const uint4* vp = (const uint4*)(g_V + (size_t)frow * D + k0);
                va = __ldg(vp); vb = __ldg(vp + 1);
            }
            v_s[fkq + 0][fm] = va.x; v_s[fkq + 1][fm] = va.y;
            v_s[fkq + 2][fm] = va.z; v_s[fkq + 3][fm] = va.w;
            v_s[fkq + 4][fm] = vb.x; v_s[fkq + 5][fm] = vb.y;
            v_s[fkq + 6][fm] = vb.z; v_s[fkq + 7][fm] = vb.w;
            const uint4* wp = (const uint4*)(g_WiH + fm * D + k0);
            uint4 wa = __ldg(wp), wb = __ldg(wp + 1);
            wi_s[fkq + 0][fm] = wa.x; wi_s[fkq + 1][fm] = wa.y;
            wi_s[fkq + 2][fm] = wa.z; wi_s[fkq + 3][fm] = wa.w;
            wi_s[fkq + 4][fm] = wb.x; wi_s[fkq + 5][fm] = wb.y;
            wi_s[fkq + 6][fm] = wb.z; wi_s[fkq + 7][fm] = wb.w;
            const uint4* np = (const uint4*)(g_WnH + fm * D + k0);
            uint4 na = __ldg(np), nb = __ldg(np + 1);
            wn_s[fkq + 0][fm] = na.x; wn_s[fkq + 1][fm] = na.y;
            wn_s[fkq + 2][fm] = na.z; wn_s[fkq + 3][fm] = na.w;
            wn_s[fkq + 4][fm] = nb.x; wn_s[fkq + 5][fm] = nb.y;
            wn_s[fkq + 6][fm] = nb.z; wn_s[fkq + 7][fm] = nb.w;
        }
        __syncthreads();

#pragma unroll
        for (int ph = 0; ph < 2; ++ph) {
            const uint32_t(*S)[SSTR] = ph ? v_s : u_s;
            const uint32_t(*W)[SSTR] = ph ? wn_s : wi_s;
#pragma unroll
            for (int kk = 0; kk < 16; kk += 8) {
                uint32_t af[4][4];
#pragma unroll
                for (int mt = 0; mt < 4; ++mt) {
                    int mr = wm * 64 + mt * 16 + grp;
                    af[mt][0] = S[kk + qid][mr];
                    af[mt][1] = S[kk + qid][mr + 8];
                    af[mt][2] = S[kk + qid + 4][mr];
                    af[mt][3] = S[kk + qid + 4][mr + 8];
                }
                uint32_t bf[4][2];
#pragma unroll
                for (int nt = 0; nt < 4; ++nt) {
                    int nc = wn * 32 + nt * 8 + grp;
                    bf[nt][0] = W[kk + qid][nc];
                    bf[nt][1] = W[kk + qid + 4][nc];
                }
#pragma unroll
                for (int mt = 0; mt < 4; ++mt)
#pragma unroll
                    for (int nt = 0; nt < 4; ++nt)
                        mma_f16(acc[mt][nt], af[mt], bf[nt]);
            }
        }
        __syncthreads();
    }

#pragma unroll
    for (int mt = 0; mt < 4; ++mt) {
#pragma unroll
        for (int nt = 0; nt < 4; ++nt) {
            int col = wn * 32 + nt * 8 + qid * 2;
            int r0 = row0 + wm * 64 + mt * 16 + grp;
            int r1 = r0 + 8;
            float x0 = acc[mt][nt][0], x1 = acc[mt][nt][1];
            float x2 = acc[mt][nt][2], x3 = acc[mt][nt][3];
            x0 = x0 > 0.f ? x0 : 0.01f * x0;
            x1 = x1 > 0.f ? x1 : 0.01f * x1;
            x2 = x2 > 0.f ? x2 : 0.01f * x2;
            x3 = x3 > 0.f ? x3 : 0.01f * x3;
            if (r0 < N)
                *(float2*)(out + (size_t)r0 * D + col) = make_float2(x0, x1);
            if (r1 < N)
                *(float2*)(out + (size_t)r1 * D + col) = make_float2(x2, x3);
        }
    }
}

// ---------------------------------------------------------------------------
extern "C" void kernel_launch(void* const* d_in, const int* in_sizes, int n_in,
                              void* d_out, int out_size) {
    const float* src_x = (const float*)d_in[0];
    const float* dst_x = (const float*)d_in[1];
    const int*   ei    = (const int*)d_in[2];    // [2, E]
    const float* ew    = (const float*)d_in[3];  // [E]
    const float* Wi    = (const float*)d_in[4];
    const float* Wn    = (const float*)d_in[5];
    float* out = (float*)d_out;

    int N = in_sizes[0] / D;
    int E = in_sizes[2] / 2;
    int nb = (N + 255) / 256;
    int n8 = N * (D / 8);
    int gmax = (n8 > E) ? n8 : E;

    hist_w_kernel<<<(E + 255) / 256, 256>>>(Wi, Wn, ei, E);
    scan_kernel<<<nb, 256>>>(N);
    permute_convert_kernel<<<(gmax + 255) / 256, 256>>>(src_x, ei, ew, E, n8, nb);
    gather_kernel<<<(N * 32 + 255) / 256, 256>>>(dst_x, N);
    fused_gemm_tc_kernel<<<(N + 127) / 128, 256>>>(out, N);
}

// round 17
// speedup vs baseline: 1.1328x; 1.1328x over previous
#include <cuda_runtime.h>
#include <cuda_fp16.h>
#include <cstdint>

#define D 128
#define MAXN 100000
#define MAXE 600000
#define SCAN_NB ((MAXN + 255) / 256)   // 391

// Scratch (device globals; no allocs allowed)
__device__ __half g_srcH[(size_t)MAXN * D];  // 25.6 MB fp16 src cache
__device__ __half g_U[(size_t)MAXN * D];     // 25.6 MB: fp16(dst + A)
__device__ __half g_V[(size_t)MAXN * D];     // 25.6 MB: fp16(dst * A)
__device__ __half g_WiH[D * D];              // fp16 W_intra
__device__ __half g_WnH[D * D];              // fp16 W_inter
__device__ int    g_count[MAXN];             // zeroed by scan each run
__device__ int    g_offs[MAXN];
__device__ int    g_state[SCAN_NB];          // lookback state; re-armed by permute
__device__ float2 g_meta[MAXE];              // (.x = src id bits, .y = w)

// ---------------------------------------------------------------------------
// Kernel 0: histogram of dst + W -> fp16
// ---------------------------------------------------------------------------
__global__ void hist_w_kernel(const float* __restrict__ Wi,
                              const float* __restrict__ Wn,
                              const int* __restrict__ ei, int E) {
    int i = blockIdx.x * blockDim.x + threadIdx.x;
    if (i < 2 * (D * D / 8)) {
        bool second = i >= (D * D / 8);
        int j = second ? i - D * D / 8 : i;
        const float* W = second ? Wn : Wi;
        __half* WH = second ? g_WnH : g_WiH;
        float4 a = __ldg((const float4*)W + 2 * j);
        float4 b = __ldg((const float4*)W + 2 * j + 1);
        __half2 h0 = __floats2half2_rn(a.x, a.y);
        __half2 h1 = __floats2half2_rn(a.z, a.w);
        __half2 h2 = __floats2half2_rn(b.x, b.y);
        __half2 h3 = __floats2half2_rn(b.z, b.w);
        uint4 o;
        o.x = *(uint32_t*)&h0;
        o.y = *(uint32_t*)&h1;
        o.z = *(uint32_t*)&h2;
        o.w = *(uint32_t*)&h3;
        ((uint4*)WH)[j] = o;
    }
    if (i < E) atomicAdd(&g_count[__ldg(&ei[E + i])], 1);
}

// ---------------------------------------------------------------------------
// Kernel 1: single-pass exclusive scan (decoupled lookback) — R9 verbatim
// ---------------------------------------------------------------------------
__global__ __launch_bounds__(256) void scan_kernel(int N) {
    __shared__ int ws[8];
    __shared__ int s_prefix;
    int tid = threadIdx.x, lane = tid & 31, wrp = tid >> 5;
    int b = blockIdx.x;
    int i = b * 256 + tid;
    int c = (i < N) ? g_count[i] : 0;
    if (i < N) g_count[i] = 0;

    int v = c;
#pragma unroll
    for (int o = 1; o < 32; o <<= 1) {
        int t = __shfl_up_sync(0xffffffffu, v, o);
        if (lane >= o) v += t;
    }
    if (lane == 31) ws[wrp] = v;
    __syncthreads();
    if (wrp == 0) {
        int s = (lane < 8) ? ws[lane] : 0;
#pragma unroll
        for (int o = 1; o < 8; o <<= 1) {
            int t = __shfl_up_sync(0xffffffffu, s, o);
            if (lane >= o) s += t;
        }
        if (lane < 8) ws[lane] = s;
    }
    __syncthreads();
    int incl = v + ((wrp > 0) ? ws[wrp - 1] : 0);
    int total = ws[7];

    if (tid == 0) {
        __threadfence();
        if (b == 0) {
            atomicExch(&g_state[0], (2 << 24) | total);
            s_prefix = 0;
        } else {
            atomicExch(&g_state[b], (1 << 24) | total);
        }
    }

    if (b > 0 && wrp == 0) {
        int agg = 0;
        int p_hi = b - 1;
        while (true) {
            int p = p_hi - lane;
            int st = (p >= 0) ? atomicAdd(&g_state[p], 0) : (2 << 24);
            int flag = st >> 24;
            int val = st & 0xFFFFFF;
            unsigned m2 = __ballot_sync(0xffffffffu, flag == 2);
            unsigned m0 = __ballot_sync(0xffffffffu, flag == 0);
            if (m2) {
                int k = __ffs(m2) - 1;
                if (m0 & ((1u << k) - 1)) continue;
                int vv = (lane <= k) ? val : 0;
#pragma unroll
                for (int o = 16; o; o >>= 1) vv += __shfl_down_sync(0xffffffffu, vv, o);
                vv = __shfl_sync(0xffffffffu, vv, 0);
                agg += vv;
                break;
            } else {
                if (m0) continue;
                int vv = val;
#pragma unroll
                for (int o = 16; o; o >>= 1) vv += __shfl_down_sync(0xffffffffu, vv, o);
                vv = __shfl_sync(0xffffffffu, vv, 0);
                agg += vv;
                p_hi -= 32;
            }
        }
        if (lane == 0) {
            s_prefix = agg;
            __threadfence();
            atomicExch(&g_state[b], (2 << 24) | (agg + total));
        }
    }
    __syncthreads();
    if (i < N) g_offs[i] = s_prefix + incl - c;
}

// ---------------------------------------------------------------------------
// Kernel 2: permute + src->fp16 convert co-scheduled — R15 verbatim
// ---------------------------------------------------------------------------
__global__ void permute_convert_kernel(const float* __restrict__ src,
                                       const int* __restrict__ ei,
                                       const float* __restrict__ ew,
                                       int E, int n8, int nb) {
    int i = blockIdx.x * blockDim.x + threadIdx.x;
    if (i < nb) g_state[i] = 0;
    if (i < n8) {
        float4 a = __ldg((const float4*)src + 2 * i);
        float4 b = __ldg((const float4*)src + 2 * i + 1);
        __half2 h0 = __floats2half2_rn(a.x, a.y);
        __half2 h1 = __floats2half2_rn(a.z, a.w);
        __half2 h2 = __floats2half2_rn(b.x, b.y);
        __half2 h3 = __floats2half2_rn(b.z, b.w);
        uint4 o;
        o.x = *(uint32_t*)&h0;
        o.y = *(uint32_t*)&h1;
        o.z = *(uint32_t*)&h2;
        o.w = *(uint32_t*)&h3;
        ((uint4*)g_srcH)[i] = o;
    }
    if (i < E) {
        int dst = __ldg(&ei[E + i]);
        int srcid = __ldg(&ei[i]);
        float w = __ldg(&ew[i]);
        int pos = atomicAdd(&g_offs[dst], 1);
        g_meta[pos] = make_float2(__int_as_float(srcid), w);
    }
}

// ---------------------------------------------------------------------------
// Kernel 3: gather — 4-deep batches (R14 champion version, regs 40)
// ---------------------------------------------------------------------------
__global__ __launch_bounds__(256) void gather_kernel(
    const float* __restrict__ dstx, int N) {
    int w = (blockIdx.x * 256 + threadIdx.x) >> 5;
    int lane = threadIdx.x & 31;
    if (w >= N) return;
    int end = __ldg(&g_offs[w]);
    int base = (w > 0) ? __ldg(&g_offs[w - 1]) : 0;
    int deg = end - base;
    float4 dv = __ldg((const float4*)(dstx + (size_t)w * D) + lane);
    float4 acc = make_float4(0.f, 0.f, 0.f, 0.f);

    for (int c0 = 0; c0 < deg; c0 += 32) {
        int cn = min(deg - c0, 32);
        float2 mv = make_float2(0.f, 0.f);
        if (lane < cn) mv = __ldg(&g_meta[base + c0 + lane]);
        for (int j = 0; j < cn; j += 4) {
            uint2 h[4];
            float wv[4];
#pragma unroll
            for (int u = 0; u < 4; ++u) {
                int idx = j + u;
                int su = __shfl_sync(0xffffffffu, __float_as_int(mv.x), idx & 31);
                float wu = __shfl_sync(0xffffffffu, mv.y, idx & 31);
                bool valid = idx < cn;
                wv[u] = valid ? wu : 0.f;
                if (valid)
                    h[u] = __ldg((const uint2*)(g_srcH + (size_t)su * D) + lane);
                else
                    h[u] = make_uint2(0u, 0u);
            }
#pragma unroll
            for (int u = 0; u < 4; ++u) {
                float2 f01 = __half22float2(*(__half2*)&h[u].x);
                float2 f23 = __half22float2(*(__half2*)&h[u].y);
                acc.x += wv[u] * f01.x;
                acc.y += wv[u] * f01.y;
                acc.z += wv[u] * f23.x;
                acc.w += wv[u] * f23.y;
            }
        }
    }
    __half2 u0 = __floats2half2_rn(dv.x + acc.x, dv.y + acc.y);
    __half2 u1 = __floats2half2_rn(dv.z + acc.z, dv.w + acc.w);
    __half2 v0 = __floats2half2_rn(dv.x * acc.x, dv.y * acc.y);
    __half2 v1 = __floats2half2_rn(dv.z * acc.z, dv.w * acc.w);
    ((uint2*)(g_U + (size_t)w * D))[lane] = make_uint2(*(uint32_t*)&u0, *(uint32_t*)&u1);
    ((uint2*)(g_V + (size_t)w * D))[lane] = make_uint2(*(uint32_t*)&v0, *(uint32_t*)&v1);
}

// ---------------------------------------------------------------------------
// Kernel 4: dual GEMM + leaky_relu, fp16 mma.m16n8k16 with cp.async pipeline.
// Row-major smem [row][16 kwords + 4 pad] per array (no transpose -> cp.async
// fills; frag LDS banks (20*grp+qid)%32 all distinct). 2 stages, groups of
// 8 cp.async per tile; mma(kt) overlaps fills of kt+1, kt+2.
// ---------------------------------------------------------------------------
#define WPR 20                         // words per row (16 data + 4 pad)
#define TILE_WORDS (128 * WPR)         // 2560 words / array / stage
#define ARR_BYTES (TILE_WORDS * 4)     // 10240 B
#define STAGE_BYTES (4 * ARR_BYTES)    // 40960 B
#define GEMM_SMEM (2 * STAGE_BYTES)    // 81920 B

__device__ __forceinline__ void cp16(uint32_t d, const void* g, int sz) {
    asm volatile("cp.async.cg.shared.global [%0], [%1], 16, %2;"
                 :: "r"(d), "l"(g), "r"(sz));
}

__device__ __forceinline__ void mma_f16(float c[4], const uint32_t a[4],
                                        const uint32_t b[2]) {
    asm volatile(
        "mma.sync.aligned.m16n8k16.row.col.f32.f16.f16.f32 "
        "{%0,%1,%2,%3},{%4,%5,%6,%7},{%8,%9},{%0,%1,%2,%3};"
        : "+f"(c[0]), "+f"(c[1]), "+f"(c[2]), "+f"(c[3])
        : "r"(a[0]), "r"(a[1]), "r"(a[2]), "r"(a[3]), "r"(b[0]), "r"(b[1]));
}

__global__ __launch_bounds__(256) void fused_gemm_tc_kernel(
    float* __restrict__ out, int N) {

    extern __shared__ uint32_t sm[];
    const uint32_t smb = (uint32_t)__cvta_generic_to_shared(sm);

    const int tid = threadIdx.x;
    const int lane = tid & 31;
    const int wid = tid >> 5;
    const int wm = wid >> 2;     // 0..1
    const int wn = wid & 3;      // 0..3
    const int grp = lane >> 2;   // 0..7
    const int qid = lane & 3;    // 0..3
    const int row0 = blockIdx.x * 128;

    const int fm = tid >> 1;            // 0..127 (row within tile)
    const int fg = (tid & 1) * 2;       // granule 0 or 2 (16B units in row)
    const int frow = row0 + fm;
    const int uv_sz = (frow < N) ? 16 : 0;   // zfill OOB rows
    const uint32_t dst_row = (uint32_t)(fm * WPR * 4 + fg * 16);
    const size_t uvsrc = (size_t)((frow < N) ? frow : 0) * D + fg * 8;
    const int wsrc = fm * D + fg * 8;

    float acc[4][4][4];
#pragma unroll
    for (int mt = 0; mt < 4; ++mt)
#pragma unroll
        for (int nt = 0; nt < 4; ++nt)
#pragma unroll
            for (int c = 0; c < 4; ++c) acc[mt][nt][c] = 0.f;

#define FILL(kt, s)                                                          \
    do {                                                                     \
        const int kh = (kt) * 32;                                            \
        uint32_t b0 = smb + (s) * STAGE_BYTES + dst_row;                     \
        cp16(b0 + 0 * ARR_BYTES,      g_U + uvsrc + kh, uv_sz);              \
        cp16(b0 + 0 * ARR_BYTES + 16, g_U + uvsrc + kh + 8, uv_sz);          \
        cp16(b0 + 1 * ARR_BYTES,      g_V + uvsrc + kh, uv_sz);              \
        cp16(b0 + 1 * ARR_BYTES + 16, g_V + uvsrc + kh + 8, uv_sz);          \
        cp16(b0 + 2 * ARR_BYTES,      g_WiH + wsrc + kh, 16);                \
        cp16(b0 + 2 * ARR_BYTES + 16, g_WiH + wsrc + kh + 8, 16);            \
        cp16(b0 + 3 * ARR_BYTES,      g_WnH + wsrc + kh, 16);                \
        cp16(b0 + 3 * ARR_BYTES + 16, g_WnH + wsrc + kh + 8, 16);            \
        asm volatile("cp.async.commit_group;");                              \
    } while (0)

    FILL(0, 0);
    FILL(1, 1);

    for (int kt = 0; kt < 4; ++kt) {
        const int s = kt & 1;
        if (kt < 3)
            asm volatile("cp.async.wait_group 1;");
        else
            asm volatile("cp.async.wait_group 0;");
        __syncthreads();

        const uint32_t* us = sm + s * (STAGE_BYTES / 4);
        const uint32_t* vs = us + TILE_WORDS;
        const uint32_t* wis = vs + TILE_WORDS;
        const uint32_t* wns = wis + TILE_WORDS;

#pragma unroll
        for (int ph = 0; ph < 2; ++ph) {
            const uint32_t* S = ph ? vs : us;
            const uint32_t* W = ph ? wns : wis;
#pragma unroll
            for (int kk = 0; kk < 16; kk += 8) {
                uint32_t af[4][4];
#pragma unroll
                for (int mt = 0; mt < 4; ++mt) {
                    int mr = wm * 64 + mt * 16 + grp;
                    af[mt][0] = S[mr * WPR + kk + qid];
                    af[mt][1] = S[(mr + 8) * WPR + kk + qid];
                    af[mt][2] = S[mr * WPR + kk + qid + 4];
                    af[mt][3] = S[(mr + 8) * WPR + kk + qid + 4];
                }
                uint32_t bf[4][2];
#pragma unroll
                for (int nt = 0; nt < 4; ++nt) {
                    int nc = wn * 32 + nt * 8 + grp;
                    bf[nt][0] = W[nc * WPR + kk + qid];
                    bf[nt][1] = W[nc * WPR + kk + qid + 4];
                }
#pragma unroll
                for (int mt = 0; mt < 4; ++mt)
#pragma unroll
                    for (int nt = 0; nt < 4; ++nt)
                        mma_f16(acc[mt][nt], af[mt], bf[nt]);
            }
        }
        __syncthreads();
        if (kt < 2) FILL(kt + 2, s);
    }

    // ---- epilogue: leaky_relu + float2 stores
#pragma unroll
    for (int mt = 0; mt < 4; ++mt) {
#pragma unroll
        for (int nt = 0; nt < 4; ++nt) {
            int col = wn * 32 + nt * 8 + qid * 2;
            int r0 = row0 + wm * 64 + mt * 16 + grp;
            int r1 = r0 + 8;
            float x0 = acc[mt][nt][0], x1 = acc[mt][nt][1];
            float x2 = acc[mt][nt][2], x3 = acc[mt][nt][3];
            x0 = x0 > 0.f ? x0 : 0.01f * x0;
            x1 = x1 > 0.f ? x1 : 0.01f * x1;
            x2 = x2 > 0.f ? x2 : 0.01f * x2;
            x3 = x3 > 0.f ? x3 : 0.01f * x3;
            if (r0 < N)
                *(float2*)(out + (size_t)r0 * D + col) = make_float2(x0, x1);
            if (r1 < N)
                *(float2*)(out + (size_t)r1 * D + col) = make_float2(x2, x3);
        }
    }
}

// ---------------------------------------------------------------------------
extern "C" void kernel_launch(void* const* d_in, const int* in_sizes, int n_in,
                              void* d_out, int out_size) {
    const float* src_x = (const float*)d_in[0];
    const float* dst_x = (const float*)d_in[1];
    const int*   ei    = (const int*)d_in[2];    // [2, E]
    const float* ew    = (const float*)d_in[3];  // [E]
    const float* Wi    = (const float*)d_in[4];
    const float* Wn    = (const float*)d_in[5];
    float* out = (float*)d_out;

    int N = in_sizes[0] / D;
    int E = in_sizes[2] / 2;
    int nb = (N + 255) / 256;
    int n8 = N * (D / 8);
    int gmax = (n8 > E) ? n8 : E;

    cudaFuncSetAttribute(fused_gemm_tc_kernel,
                         cudaFuncAttributeMaxDynamicSharedMemorySize, GEMM_SMEM);

    hist_w_kernel<<<(E + 255) / 256, 256>>>(Wi, Wn, ei, E);
    scan_kernel<<<nb, 256>>>(N);
    permute_convert_kernel<<<(gmax + 255) / 256, 256>>>(src_x, ei, ew, E, n8, nb);
    gather_kernel<<<(N * 32 + 255) / 256, 256>>>(dst_x, N);
    fused_gemm_tc_kernel<<<(N + 127) / 128, 256, GEMM_SMEM>>>(out, N);
}